// round 16
// baseline (speedup 1.0000x reference)
#include <cuda_runtime.h>
#include <cstdint>

#define TSTEPS 2048
#define BATCH  32
#define EDIM   512
#define HDIM   512
#define NCTA   128

typedef unsigned long long ull;

__device__ float    g_embT[(size_t)TSTEPS * EDIM * BATCH]; // [t][k][b]
__device__ float    g_h[2][HDIM * BATCH];                  // [col][b]
__device__ unsigned g_grp[8];                              // tree barrier: 16 CTAs/group
__device__ unsigned g_root;

__device__ __forceinline__ ull ffma2(ull a, ull b, ull c) {
    ull d;
    asm("fma.rn.f32x2 %0, %1, %2, %3;" : "=l"(d) : "l"(a), "l"(b), "l"(c));
    return d;
}
__device__ __forceinline__ ull fadd2(ull a, ull b) {
    ull d;
    asm("add.rn.f32x2 %0, %1, %2;" : "=l"(d) : "l"(a), "l"(b));
    return d;
}
__device__ __forceinline__ ull dup2(float v) {
    ull d; unsigned u = __float_as_uint(v);
    asm("mov.b64 %0, {%1, %1};" : "=l"(d) : "r"(u));
    return d;
}
__device__ __forceinline__ float sigf(float x) { return 1.0f / (1.0f + __expf(-x)); }
__device__ __forceinline__ float tanhf_fast(float x) {
    return __fmaf_rn(2.0f, sigf(2.0f * x), -1.0f);
}

// ---------------------------------------------------------------------------
__global__ void k_init() {
    int i = blockIdx.x * blockDim.x + threadIdx.x;
    if (i < 2 * HDIM * BATCH) ((float*)g_h)[i] = 0.0f;
    if (i < 8) g_grp[i] = 0u;
    if (i == 8) g_root = 0u;
}

// ---------------------------------------------------------------------------
// Transpose emb[t][b][k] -> g_embT[t][k][b]. One CTA per t. (Measured-passing.)
// ---------------------------------------------------------------------------
__global__ void __launch_bounds__(256) k_transp(const float* __restrict__ emb) {
    extern __shared__ float tile[];       // [32 b][516] padded
    const int tid = threadIdx.x;
    const int t   = blockIdx.x;
    const float4* src = (const float4*)(emb + (size_t)t * (BATCH * EDIM));
    #pragma unroll
    for (int j = 0; j < 16; j++) {
        int fidx = j * 256 + tid;
        int b  = fidx >> 7;
        int kq = fidx & 127;
        float4 v = src[b * 128 + kq];
        *(float4*)&tile[b * 516 + kq * 4] = v;
    }
    __syncthreads();
    float* dst = g_embT + (size_t)t * (EDIM * BATCH);
    #pragma unroll
    for (int j = 0; j < 16; j++) {
        int oidx = j * 256 + tid;
        int k  = oidx >> 3;
        int bq = oidx & 7;
        float4 v;
        v.x = tile[(bq * 4 + 0) * 516 + k];
        v.y = tile[(bq * 4 + 1) * 516 + k];
        v.z = tile[(bq * 4 + 2) * 516 + k];
        v.w = tile[(bq * 4 + 3) * 516 + k];
        *(float4*)&dst[k * 32 + bq * 4] = v;
    }
}

// ---------------------------------------------------------------------------
// Fused persistent LSTM (R14 structure). W slices stored PRE-DUPLICATED in
// smem: per k the compute reads 2 conflict-free LDS.128 (no dup2 MOVs) ->
// 10 instrs per k instead of 13. smem ~166KB, 1 CTA/SM.
// ---------------------------------------------------------------------------
#define LOADC(base, kc, A0, A1)                                            \
    _Pragma("unroll")                                                      \
    for (int k = 0; k < 8; k++) {                                          \
        asm("ld.global.cg.v2.u64 {%0,%1}, [%2];"                           \
            : "=l"(A0[k]), "=l"(A1[k])                                     \
            : "l"((base) + ((kc) * 8 + k) * 32));                          \
    }

#define COMPC(Wt, kc, A0, A1)                                              \
    _Pragma("unroll")                                                      \
    for (int k = 0; k < 8; k++) {                                          \
        const ull* wp = (Wt) + (size_t)(k0 + (kc) * 8 + k) * 16 + c_grp * 4; \
        ulonglong2 w01 = *(const ulonglong2*)wp;                           \
        ulonglong2 w23 = *(const ulonglong2*)(wp + 2);                     \
        acc[0] = ffma2(A0[k], w01.x, acc[0]);                              \
        acc[1] = ffma2(A1[k], w01.x, acc[1]);                              \
        acc[2] = ffma2(A0[k], w01.y, acc[2]);                              \
        acc[3] = ffma2(A1[k], w01.y, acc[3]);                              \
        acc[4] = ffma2(A0[k], w23.x, acc[4]);                              \
        acc[5] = ffma2(A1[k], w23.x, acc[5]);                              \
        acc[6] = ffma2(A0[k], w23.y, acc[6]);                              \
        acc[7] = ffma2(A1[k], w23.y, acc[7]);                              \
    }

#define MATMUL(base, Wt)                                                   \
    {                                                                      \
        ull pa0[8], pa1[8], pb0[8], pb1[8];                                \
        LOADC(base, 0, pa0, pa1);                                          \
        LOADC(base, 1, pb0, pb1);                                          \
        COMPC(Wt, 0, pa0, pa1);                                            \
        LOADC(base, 2, pa0, pa1);                                          \
        COMPC(Wt, 1, pb0, pb1);                                            \
        LOADC(base, 3, pb0, pb1);                                          \
        COMPC(Wt, 2, pa0, pa1);                                            \
        COMPC(Wt, 3, pb0, pb1);                                            \
    }

__global__ void __launch_bounds__(512, 1) k_rec(
    const float* __restrict__ whi, const float* __restrict__ whf,
    const float* __restrict__ whg, const float* __restrict__ who,
    const float* __restrict__ wxi, const float* __restrict__ wxf,
    const float* __restrict__ wxg, const float* __restrict__ wxo,
    const float* __restrict__ bi,  const float* __restrict__ bf,
    const float* __restrict__ bg,  const float* __restrict__ bo,
    float* __restrict__ out)
{
    extern __shared__ ull sr[];
    ull*   whs   = sr;                    // [512 k][16 lc] dup'd  = 8192 ull
    ull*   wxs   = sr + 8192;             // [512 k][16 lc] dup'd  = 8192 ull
    ull*   red   = sr + 16384;            // [16 w][16 c x 18]     = 4608 ull
    ull*   sgu   = sr + 20992;            // [16 c][16 bp]         = 256 ull
    float* sgf   = (float*)sgu;
    float* ost   = (float*)(sr + 21248);  // [32 b][4 hu]          = 64 ull
    float* sbias = (float*)(sr + 21312);  // [16 lc]               = 8 ull
    // total 21320 ull = 170560 B

    const int tid  = threadIdx.x;
    const int lane = tid & 31;
    const int wrp  = tid >> 5;           // 0..15
    const int cta  = blockIdx.x;

    // Stage Wh + Wx slices DUPLICATED: [k*16 + lc] = (w, w), col = cta*4+(lc&3).
    for (int i = tid; i < 8192; i += 512) {
        int k = i >> 4, lc = i & 15;
        int g = lc >> 2, hu = lc & 3;
        const float* Wh = (g == 0) ? whi : (g == 1) ? whf : (g == 2) ? whg : who;
        const float* Wx = (g == 0) ? wxi : (g == 1) ? wxf : (g == 2) ? wxg : wxo;
        whs[i] = dup2(Wh[(size_t)k * HDIM + cta * 4 + hu]);
        wxs[i] = dup2(Wx[(size_t)k * HDIM + cta * 4 + hu]);
    }
    if (tid < 16) {
        int g = tid >> 2, hu = tid & 3;
        const float* bp = (g == 0) ? bi : (g == 1) ? bf : (g == 2) ? bg : bo;
        sbias[tid] = bp[cta * 4 + hu];
    }
    __syncthreads();

    const int b_grp = lane >> 2;
    const int c_grp = lane & 3;
    const int k0    = wrp * 32;
    const int hu_g  = tid >> 5;          // gate phase (tid<128)
    const int b_g   = tid & 31;
    const int cl_r  = tid >> 4;          // reduce phase (tid<256)
    const int bp_r  = tid & 15;
    float c_state = 0.0f;

    unsigned* grpp  = &g_grp[cta >> 4];
    unsigned* rootp = &g_root;

    for (int t = 0; t < TSTEPS; t++) {
        const int pin = t & 1;

        ull acc[8];
        #pragma unroll
        for (int j = 0; j < 8; j++) acc[j] = 0ull;

        // Phase A: input-projection matmul (h-independent, overlaps wait).
        {
            const float* eb = g_embT + (size_t)t * (EDIM * BATCH) + k0 * 32 + b_grp * 4;
            MATMUL(eb, wxs);
        }

        // Barrier wait: h(t) published by all CTAs (arrive was at end of t-1).
        if (t > 0) {
            if (tid == 0) {
                unsigned target = 8u * (unsigned)t;
                unsigned v;
                do {
                    asm volatile("ld.acquire.gpu.global.u32 %0, [%1];"
                                 : "=r"(v) : "l"(rootp) : "memory");
                } while (v < target);
            }
            __syncthreads();
        }

        // Phase B: recurrent matmul.
        {
            const float* hb = g_h[pin] + k0 * 32 + b_grp * 4;
            MATMUL(hb, whs);
        }

        #pragma unroll
        for (int j = 0; j < 4; j++) {
            ulonglong2 v;
            v.x = acc[j * 2];
            v.y = acc[j * 2 + 1];
            *(ulonglong2*)&red[wrp * 288 + (c_grp * 4 + j) * 18 + b_grp * 2] = v;
        }
        __syncthreads();

        // Parallel packed reduce + bias: 256 threads, one (lc, b-pair) each.
        if (tid < 256) {
            ull v[16];
            #pragma unroll
            for (int w = 0; w < 16; w++)
                v[w] = red[w * 288 + cl_r * 18 + bp_r];
            #pragma unroll
            for (int st = 8; st >= 1; st >>= 1)
                #pragma unroll
                for (int w = 0; w < st; w++) v[w] = fadd2(v[w], v[w + st]);
            sgu[cl_r * 16 + bp_r] = fadd2(v[0], dup2(sbias[cl_r]));
        }
        __syncthreads();

        if (tid < 128) {
            float s0 = sgf[(0 * 4 + hu_g) * 32 + b_g];
            float s1 = sgf[(1 * 4 + hu_g) * 32 + b_g];
            float s2 = sgf[(2 * 4 + hu_g) * 32 + b_g];
            float s3 = sgf[(3 * 4 + hu_g) * 32 + b_g];
            float ig = sigf(s0);
            float fg = sigf(s1);
            float gg = tanhf_fast(s2);
            float og = sigf(s3);
            c_state = fg * c_state + ig * gg;
            float hval = og * tanhf_fast(c_state);

            int col = cta * 4 + hu_g;
            __stcg(&((float*)g_h[pin ^ 1])[col * 32 + b_g], hval);
            ost[b_g * 4 + hu_g] = hval;
        }
        __syncthreads();     // h stores done CTA-wide

        // Arrive (wait happens after next step's Phase A).
        if (t < TSTEPS - 1 && tid == 0) {
            unsigned old;
            asm volatile("atom.acq_rel.gpu.global.add.u32 %0, [%1], 1;"
                         : "=r"(old) : "l"(grpp) : "memory");
            if (old == 16u * (unsigned)(t + 1) - 1u) {
                asm volatile("red.release.gpu.global.add.u32 [%0], 1;"
                             :: "l"(rootp) : "memory");
            }
        }

        // out store overlaps other CTAs' arrivals.
        if (tid >= 128 && tid < 160) {
            int b = tid - 128;
            float4 o4 = *(const float4*)&ost[b * 4];
            *(float4*)&out[(size_t)t * (BATCH * HDIM) + (size_t)b * HDIM + cta * 4] = o4;
        }
    }
}

// ---------------------------------------------------------------------------
extern "C" void kernel_launch(void* const* d_in, const int* in_sizes, int n_in,
                              void* d_out, int out_size) {
    const float* emb = (const float*)d_in[0];
    const float* wxi = (const float*)d_in[1];
    const float* whi = (const float*)d_in[2];
    const float* bi  = (const float*)d_in[3];
    const float* wxf = (const float*)d_in[4];
    const float* whf = (const float*)d_in[5];
    const float* bf  = (const float*)d_in[6];
    const float* wxg = (const float*)d_in[7];
    const float* whg = (const float*)d_in[8];
    const float* bg  = (const float*)d_in[9];
    const float* wxo = (const float*)d_in[10];
    const float* who = (const float*)d_in[11];
    const float* bo  = (const float*)d_in[12];
    float* out = (float*)d_out;

    cudaFuncSetAttribute(k_transp, cudaFuncAttributeMaxDynamicSharedMemorySize, 66048);
    cudaFuncSetAttribute(k_rec,    cudaFuncAttributeMaxDynamicSharedMemorySize, 171008);

    k_transp<<<TSTEPS, 256, 66048>>>(emb);
    k_init<<<128, 256>>>();
    k_rec<<<NCTA, 512, 170560>>>(whi, whf, whg, who,
                                 wxi, wxf, wxg, wxo,
                                 bi, bf, bg, bo, out);
}

// round 17
// speedup vs baseline: 1.3038x; 1.3038x over previous
#include <cuda_runtime.h>
#include <cstdint>

#define TSTEPS 2048
#define BATCH  32
#define EDIM   512
#define HDIM   512
#define NCTA   128

typedef unsigned long long ull;

__device__ float    g_embT[(size_t)TSTEPS * EDIM * BATCH]; // [t][k][b]
__device__ float    g_h[2][HDIM * BATCH];                  // [col][b]
__device__ unsigned g_grp[8];                              // tree barrier: 16 CTAs/group
__device__ unsigned g_root;

__device__ __forceinline__ ull ffma2(ull a, ull b, ull c) {
    ull d;
    asm("fma.rn.f32x2 %0, %1, %2, %3;" : "=l"(d) : "l"(a), "l"(b), "l"(c));
    return d;
}
__device__ __forceinline__ ull fadd2(ull a, ull b) {
    ull d;
    asm("add.rn.f32x2 %0, %1, %2;" : "=l"(d) : "l"(a), "l"(b));
    return d;
}
__device__ __forceinline__ ull dup2(float v) {
    ull d; unsigned u = __float_as_uint(v);
    asm("mov.b64 %0, {%1, %1};" : "=l"(d) : "r"(u));
    return d;
}
__device__ __forceinline__ float sigf(float x) { return 1.0f / (1.0f + __expf(-x)); }
__device__ __forceinline__ float tanhf_fast(float x) {
    return __fmaf_rn(2.0f, sigf(2.0f * x), -1.0f);
}

// ---------------------------------------------------------------------------
__global__ void k_init() {
    int i = blockIdx.x * blockDim.x + threadIdx.x;
    if (i < 2 * HDIM * BATCH) ((float*)g_h)[i] = 0.0f;
    if (i < 8) g_grp[i] = 0u;
    if (i == 8) g_root = 0u;
}

// ---------------------------------------------------------------------------
// Transpose emb[t][b][k] -> g_embT[t][k][b]. One CTA per t. (Measured-passing.)
// ---------------------------------------------------------------------------
__global__ void __launch_bounds__(256) k_transp(const float* __restrict__ emb) {
    extern __shared__ float tile[];       // [32 b][516] padded
    const int tid = threadIdx.x;
    const int t   = blockIdx.x;
    const float4* src = (const float4*)(emb + (size_t)t * (BATCH * EDIM));
    #pragma unroll
    for (int j = 0; j < 16; j++) {
        int fidx = j * 256 + tid;
        int b  = fidx >> 7;
        int kq = fidx & 127;
        float4 v = src[b * 128 + kq];
        *(float4*)&tile[b * 516 + kq * 4] = v;
    }
    __syncthreads();
    float* dst = g_embT + (size_t)t * (EDIM * BATCH);
    #pragma unroll
    for (int j = 0; j < 16; j++) {
        int oidx = j * 256 + tid;
        int k  = oidx >> 3;
        int bq = oidx & 7;
        float4 v;
        v.x = tile[(bq * 4 + 0) * 516 + k];
        v.y = tile[(bq * 4 + 1) * 516 + k];
        v.z = tile[(bq * 4 + 2) * 516 + k];
        v.w = tile[(bq * 4 + 3) * 516 + k];
        *(float4*)&dst[k * 32 + bq * 4] = v;
    }
}

// ---------------------------------------------------------------------------
// Fused persistent LSTM (R14 microkernel: undup W float4 + dup2-in-regs).
// Tail uses SCOPED named barriers so warps 8..15 skip the reduce/gate tail
// and start the next step's input-projection matmul immediately.
// ---------------------------------------------------------------------------
#define LOADC(base, kc, A0, A1)                                            \
    _Pragma("unroll")                                                      \
    for (int k = 0; k < 8; k++) {                                          \
        asm("ld.global.cg.v2.u64 {%0,%1}, [%2];"                           \
            : "=l"(A0[k]), "=l"(A1[k])                                     \
            : "l"((base) + ((kc) * 8 + k) * 32));                          \
    }

#define COMPC(Wt, kc, A0, A1)                                              \
    _Pragma("unroll")                                                      \
    for (int k = 0; k < 8; k++) {                                          \
        float4 wv = *(const float4*)&(Wt)[(k0 + (kc) * 8 + k) * 16 + c_grp * 4]; \
        ull w0 = dup2(wv.x), w1 = dup2(wv.y), w2 = dup2(wv.z), w3 = dup2(wv.w);  \
        acc[0] = ffma2(A0[k], w0, acc[0]);                                 \
        acc[1] = ffma2(A1[k], w0, acc[1]);                                 \
        acc[2] = ffma2(A0[k], w1, acc[2]);                                 \
        acc[3] = ffma2(A1[k], w1, acc[3]);                                 \
        acc[4] = ffma2(A0[k], w2, acc[4]);                                 \
        acc[5] = ffma2(A1[k], w2, acc[5]);                                 \
        acc[6] = ffma2(A0[k], w3, acc[6]);                                 \
        acc[7] = ffma2(A1[k], w3, acc[7]);                                 \
    }

#define MATMUL(base, Wt)                                                   \
    {                                                                      \
        ull pa0[8], pa1[8], pb0[8], pb1[8];                                \
        LOADC(base, 0, pa0, pa1);                                          \
        LOADC(base, 1, pb0, pb1);                                          \
        COMPC(Wt, 0, pa0, pa1);                                            \
        LOADC(base, 2, pa0, pa1);                                          \
        COMPC(Wt, 1, pb0, pb1);                                            \
        LOADC(base, 3, pb0, pb1);                                          \
        COMPC(Wt, 2, pa0, pa1);                                            \
        COMPC(Wt, 3, pb0, pb1);                                            \
    }

#define BARN(id, cnt) \
    asm volatile("bar.sync %0, %1;" :: "r"(id), "r"(cnt) : "memory")

__global__ void __launch_bounds__(512, 1) k_rec(
    const float* __restrict__ whi, const float* __restrict__ whf,
    const float* __restrict__ whg, const float* __restrict__ who,
    const float* __restrict__ wxi, const float* __restrict__ wxf,
    const float* __restrict__ wxg, const float* __restrict__ wxo,
    const float* __restrict__ bi,  const float* __restrict__ bf,
    const float* __restrict__ bg,  const float* __restrict__ bo,
    float* __restrict__ out)
{
    extern __shared__ ull sr[];
    float* whsf  = (float*)sr;            // [512 k][16 lc] floats = 4096 ull
    float* wxsf  = (float*)(sr + 4096);   // [512 k][16 lc] floats = 4096 ull
    ull*   red   = sr + 8192;             // [16 w][16 c x 18]      = 4608 ull
    ull*   sgu   = sr + 12800;            // [16 c][16 bp]          = 256 ull
    float* sgf   = (float*)sgu;
    float* ost   = (float*)(sr + 13056);  // [32 b][4 hu]           = 64 ull
    float* sbias = (float*)(sr + 13120);  // [16 lc]                = 8 ull
    // total 13128 ull = 105024 B

    const int tid  = threadIdx.x;
    const int lane = tid & 31;
    const int wrp  = tid >> 5;           // 0..15
    const int cta  = blockIdx.x;

    // Stage Wh + Wx slices undup'd: [k*16 + lc], col = cta*4 + (lc&3).
    for (int i = tid; i < 8192; i += 512) {
        int k = i >> 4, lc = i & 15;
        int g = lc >> 2, hu = lc & 3;
        const float* Wh = (g == 0) ? whi : (g == 1) ? whf : (g == 2) ? whg : who;
        const float* Wx = (g == 0) ? wxi : (g == 1) ? wxf : (g == 2) ? wxg : wxo;
        whsf[i] = Wh[(size_t)k * HDIM + cta * 4 + hu];
        wxsf[i] = Wx[(size_t)k * HDIM + cta * 4 + hu];
    }
    if (tid < 16) {
        int g = tid >> 2, hu = tid & 3;
        const float* bp = (g == 0) ? bi : (g == 1) ? bf : (g == 2) ? bg : bo;
        sbias[tid] = bp[cta * 4 + hu];
    }
    __syncthreads();

    const int b_grp = lane >> 2;
    const int c_grp = lane & 3;
    const int k0    = wrp * 32;
    const int hu_g  = tid >> 5;          // gate phase (tid<128)
    const int b_g   = tid & 31;
    const int cl_r  = tid >> 4;          // reduce phase (tid<256)
    const int bp_r  = tid & 15;
    float c_state = 0.0f;

    unsigned* grpp  = &g_grp[cta >> 4];
    unsigned* rootp = &g_root;

    for (int t = 0; t < TSTEPS; t++) {
        const int pin = t & 1;

        ull acc[8];
        #pragma unroll
        for (int j = 0; j < 8; j++) acc[j] = 0ull;

        // Phase A: input-projection matmul (h-independent). Warps 8..15 reach
        // this while warps 0..7 still run the previous step's tail.
        {
            const float* eb = g_embT + (size_t)t * (EDIM * BATCH) + k0 * 32 + b_grp * 4;
            MATMUL(eb, wxsf);
        }

        // SYNC_W: full-CTA barrier after root poll. Also orders red(t-1)
        // consumption before red(t) writes below.
        if (t > 0) {
            if (tid == 0) {
                unsigned target = 8u * (unsigned)t;
                unsigned v;
                do {
                    asm volatile("ld.acquire.gpu.global.u32 %0, [%1];"
                                 : "=r"(v) : "l"(rootp) : "memory");
                } while (v < target);
            }
            __syncthreads();
        }

        // Phase B: recurrent matmul.
        {
            const float* hb = g_h[pin] + k0 * 32 + b_grp * 4;
            MATMUL(hb, whsf);
        }

        #pragma unroll
        for (int j = 0; j < 4; j++) {
            ulonglong2 v;
            v.x = acc[j * 2];
            v.y = acc[j * 2 + 1];
            *(ulonglong2*)&red[wrp * 288 + (c_grp * 4 + j) * 18 + b_grp * 2] = v;
        }
        __syncthreads();   // SYNC1: red written by all 16 warps, read by warps 0..7

        // ---- Tail: warps 8..15 skip everything below and loop to Phase A ----
        if (tid < 256) {
            // Parallel packed reduce + bias: one (lc, b-pair) per thread.
            ull v[16];
            #pragma unroll
            for (int w = 0; w < 16; w++)
                v[w] = red[w * 288 + cl_r * 18 + bp_r];
            #pragma unroll
            for (int st = 8; st >= 1; st >>= 1)
                #pragma unroll
                for (int w = 0; w < st; w++) v[w] = fadd2(v[w], v[w + st]);
            sgu[cl_r * 16 + bp_r] = fadd2(v[0], dup2(sbias[cl_r]));

            BARN(2, 256);  // SYNC2: sgu ready for gate threads

            if (tid < 128) {
                float s0 = sgf[(0 * 4 + hu_g) * 32 + b_g];
                float s1 = sgf[(1 * 4 + hu_g) * 32 + b_g];
                float s2 = sgf[(2 * 4 + hu_g) * 32 + b_g];
                float s3 = sgf[(3 * 4 + hu_g) * 32 + b_g];
                float ig = sigf(s0);
                float fg = sigf(s1);
                float gg = tanhf_fast(s2);
                float og = sigf(s3);
                c_state = fg * c_state + ig * gg;
                float hval = og * tanhf_fast(c_state);

                int col = cta * 4 + hu_g;
                __stcg(&((float*)g_h[pin ^ 1])[col * 32 + b_g], hval);
                ost[b_g * 4 + hu_g] = hval;
            }

            if (tid < 160) {
                BARN(3, 160);  // SYNC3: h + ost stores visible to tid0 / out-storers

                if (tid == 0 && t < TSTEPS - 1) {
                    unsigned old;
                    asm volatile("atom.acq_rel.gpu.global.add.u32 %0, [%1], 1;"
                                 : "=r"(old) : "l"(grpp) : "memory");
                    if (old == 16u * (unsigned)(t + 1) - 1u) {
                        asm volatile("red.release.gpu.global.add.u32 [%0], 1;"
                                     :: "l"(rootp) : "memory");
                    }
                }
                if (tid >= 128) {
                    int b = tid - 128;
                    float4 o4 = *(const float4*)&ost[b * 4];
                    *(float4*)&out[(size_t)t * (BATCH * HDIM) + (size_t)b * HDIM + cta * 4] = o4;
                }
            }
        }
    }
}

// ---------------------------------------------------------------------------
extern "C" void kernel_launch(void* const* d_in, const int* in_sizes, int n_in,
                              void* d_out, int out_size) {
    const float* emb = (const float*)d_in[0];
    const float* wxi = (const float*)d_in[1];
    const float* whi = (const float*)d_in[2];
    const float* bi  = (const float*)d_in[3];
    const float* wxf = (const float*)d_in[4];
    const float* whf = (const float*)d_in[5];
    const float* bf  = (const float*)d_in[6];
    const float* wxg = (const float*)d_in[7];
    const float* whg = (const float*)d_in[8];
    const float* bg  = (const float*)d_in[9];
    const float* wxo = (const float*)d_in[10];
    const float* who = (const float*)d_in[11];
    const float* bo  = (const float*)d_in[12];
    float* out = (float*)d_out;

    cudaFuncSetAttribute(k_transp, cudaFuncAttributeMaxDynamicSharedMemorySize, 66048);
    cudaFuncSetAttribute(k_rec,    cudaFuncAttributeMaxDynamicSharedMemorySize, 105472);

    k_transp<<<TSTEPS, 256, 66048>>>(emb);
    k_init<<<128, 256>>>();
    k_rec<<<NCTA, 512, 105024>>>(whi, whf, whg, who,
                                 wxi, wxf, wxg, wxo,
                                 bi, bf, bg, bo, out);
}